// round 4
// baseline (speedup 1.0000x reference)
#include <cuda_runtime.h>
#include <math.h>

// ---------------- problem constants ----------------
#define NB    4
#define NLVL  3
#define NA    9
#define NC    80
#define PRE   1000
#define TOPN  100
#define NCAP  8192
#define NCH   47          // ceil(3000/64)
#define NTILE 1128        // NCH*(NCH+1)/2 upper-triangle 64x64 tiles
#define LOG_MAX_F 4.135166556742356f
#define IMG_OFF 641.0f

typedef unsigned long long u64;

// ---------------- device scratch (zero at load; re-zeroed by last kernel each run) ----------------
__device__ unsigned int g_cnt  [12];
__device__ unsigned int g_done [12];
__device__ unsigned int g_need [12];
__device__ unsigned int g_mdone[NB];
__device__ unsigned int g_kdone[NB];
__device__ u64          g_cand[12][NCAP];
__device__ float        g_rois[NB][3000][6];
__device__ u64          g_skey[NB][3000];
__device__ int          g_spos[NB][3008];
__device__ float        g_sx1[NB][3008], g_sy1[NB][3008], g_sx2[NB][3008], g_sy2[NB][3008], g_sar[NB][3008];
__device__ u64          g_mask[NB][3000 * NCH];

// ---------------- helpers ----------------
__device__ __forceinline__ void bitonic_desc(u64* s, int n, int tid, int nt) {
    for (int k = 2; k <= n; k <<= 1) {
        for (int j = k >> 1; j > 0; j >>= 1) {
            for (int i = tid; i < n; i += nt) {
                int ixj = i ^ j;
                if (ixj > i) {
                    u64 a = s[i], b = s[ixj];
                    bool sw = ((i & k) == 0) ? (a < b) : (a > b);
                    if (sw) { s[i] = b; s[ixj] = a; }
                }
            }
            __syncthreads();
        }
    }
}

__device__ __forceinline__ void push_cand(int id, int m, int HW, float x) {
    int ch = m / HW;
    int pp = m - ch * HW;
    int a  = ch / NC;
    int cc = ch - a * NC;
    unsigned int f = (unsigned int)((pp * NA + a) * NC + cc);
    float score = 1.0f / (1.0f + expf(-x));
    u64 k64 = ((u64)__float_as_uint(score) << 32) | (u64)(0xFFFFFFFFu - f);
    unsigned int pos = atomicAdd(&g_cnt[id], 1u);
    if (pos < NCAP) g_cand[id][pos] = k64;
}

// ---------------- kernel 1: speculative gather (pure stream) + last-block validation ----------------
__global__ void __launch_bounds__(256) passA_kernel(const float4* __restrict__ c0,
                                                    const float4* __restrict__ c1,
                                                    const float4* __restrict__ c2) {
    int bx = blockIdx.x;
    int lvl, li, per, nvec, HW;
    const float4* p;
    if (bx < 1152)      { lvl = 0; li = bx;        per = 288; nvec = 1152000; HW = 6400; p = c0; }
    else if (bx < 1440) { lvl = 1; li = bx - 1152; per = 72;  nvec = 288000;  HW = 1600; p = c1; }
    else                { lvl = 2; li = bx - 1440; per = 24;  nvec = 72000;   HW = 400;  p = c2; }
    int b = li / per;
    int chunk = li - b * per;
    int len = nvec / per;
    int start = chunk * len;
    p += (size_t)b * nvec;
    int id = b * 3 + lvl;
    float specT = (lvl == 0) ? 3.39f : ((lvl == 1) ? 2.99f : 2.54f);

    int e = start + len;
    for (int base = start + threadIdx.x; base < e; base += 256 * 8) {
        float4 v[8];
        bool ok[8];
#pragma unroll
        for (int u = 0; u < 8; u++) {
            int idx = base + u * 256;
            ok[u] = idx < e;
            v[u] = ok[u] ? p[idx] : make_float4(0.f, 0.f, 0.f, 0.f);
        }
#pragma unroll
        for (int u = 0; u < 8; u++) {
            if (!ok[u]) continue;
            int idx = base + u * 256;
            float c[4] = {v[u].x, v[u].y, v[u].z, v[u].w};
#pragma unroll
            for (int q = 0; q < 4; q++) {
                if (c[q] >= specT) push_cand(id, idx * 4 + q, HW, c[q]);
            }
        }
    }

    // last block for this (b,lvl) validates the speculative count
    __syncthreads();
    __shared__ int s_last;
    if (threadIdx.x == 0) {
        __threadfence();
        unsigned int o = atomicAdd(&g_done[id], 1u);
        s_last = (o == (unsigned int)(per - 1));
    }
    __syncthreads();
    if (s_last && threadIdx.x == 0) {
        unsigned int cnt = g_cnt[id];
        int ok = (cnt >= PRE && cnt <= NCAP);
        g_need[id] = ok ? 0u : 1u;
        if (!ok) g_cnt[id] = 0;
    }
}

// ---------------- kernel 2: (fallback gather) + per-level sort/decode + last-block merge ----------------
__global__ void topk_decode_kernel(const float4* __restrict__ c0,
                                   const float4* __restrict__ c1,
                                   const float4* __restrict__ c2,
                                   const float* __restrict__ loc0,
                                   const float* __restrict__ loc1,
                                   const float* __restrict__ loc2,
                                   const float* __restrict__ info) {
    extern __shared__ u64 sk[];      // 64KB: hist(16KB) -> sort keys -> merge buffer
    int lvl = blockIdx.x % 3, b = blockIdx.x / 3;
    int id = b * 3 + lvl;
    int tid = threadIdx.x, nt = blockDim.x;
    const int Ht[3] = {80, 40, 20}, St[3] = {8, 16, 32};
    const int Nv[3] = {1152000, 288000, 72000};
    int H = Ht[lvl], W = H, stride = St[lvl];
    const float* loc = (lvl == 0) ? loc0 : ((lvl == 1) ? loc1 : loc2);
    int HW = H * W;

    // ---- fallback: exact gather on spec-miss (rare) ----
    if (g_need[id] != 0u) {
        unsigned int* hist = (unsigned int*)sk;
        __shared__ unsigned int segsum[256];
        __shared__ unsigned int s_thr;
        int nvec = Nv[lvl];
        const float4* p = ((lvl == 0) ? c0 : ((lvl == 1) ? c1 : c2)) + (size_t)b * nvec;

        for (int i = tid; i < 4096; i += nt) hist[i] = 0;
        __syncthreads();
        for (int i = tid; i < nvec; i += nt) {
            float4 v = p[i];
            float c[4] = {v.x, v.y, v.z, v.w};
#pragma unroll
            for (int q = 0; q < 4; q++) {
                if (c[q] >= 1.0f) {
                    unsigned int key = __float_as_uint(c[q]) | 0x80000000u;
                    atomicAdd(&hist[key >> 20], 1u);
                }
            }
        }
        __syncthreads();
        if (tid < 256) {
            unsigned int s = 0;
#pragma unroll
            for (int q = 0; q < 16; q++) s += hist[tid * 16 + q];
            segsum[tid] = s;
        }
        __syncthreads();
        for (int d = 1; d < 256; d <<= 1) {
            unsigned int v = 0;
            if (tid < 256) {
                v = segsum[tid];
                if (tid + d < 256) v += segsum[tid + d];
            }
            __syncthreads();
            if (tid < 256) segsum[tid] = v;
            __syncthreads();
        }
        if (tid < 256) {
            unsigned int cum = (tid < 255) ? segsum[tid + 1] : 0u;
            for (int q = 15; q >= 0; q--) {
                int bin = tid * 16 + q;
                unsigned int hv = hist[bin];
                cum += hv;
                if (cum >= PRE && (cum - hv) < PRE) s_thr = ((unsigned int)bin) << 20;
            }
        }
        __syncthreads();
        unsigned int thr = s_thr;
        for (int i = tid; i < nvec; i += nt) {
            float4 v = p[i];
            float c[4] = {v.x, v.y, v.z, v.w};
#pragma unroll
            for (int q = 0; q < 4; q++) {
                if (c[q] >= 1.0f) {
                    unsigned int key = __float_as_uint(c[q]) | 0x80000000u;
                    if (key >= thr) push_cand(id, i * 4 + q, HW, c[q]);
                }
            }
        }
        __syncthreads();
    }

    // ---- sort candidates (n = next pow2 of count) ----
    unsigned int cnt = atomicAdd(&g_cnt[id], 0u);
    if (cnt > NCAP) cnt = NCAP;
    int n = 1024;
    while (n < (int)cnt) n <<= 1;
    for (int i = tid; i < n; i += nt)
        sk[i] = (i < (int)cnt) ? g_cand[id][i] : 0ull;
    __syncthreads();
    bitonic_desc(sk, n, tid, nt);

    float imh = info[b * 5 + 0];
    float imw = info[b * 5 + 1];

    // ---- decode top-1000 ----
    for (int r = tid; r < PRE; r += nt) {
        u64 key = sk[r];
        int mpos = lvl * PRE + r;
        float* row = g_rois[b][mpos];
        if (key == 0ull) {
            row[0] = row[1] = row[2] = row[3] = row[4] = row[5] = 0.0f;
            g_skey[b][mpos] = (u64)(0xFFFFFFFFu - (unsigned int)mpos);
            continue;
        }
        unsigned int f = 0xFFFFFFFFu - (unsigned int)(key & 0xFFFFFFFFu);
        float score = __uint_as_float((unsigned int)(key >> 32));
        g_skey[b][mpos] = ((u64)__float_as_uint(score) << 32) |
                          (u64)(0xFFFFFFFFu - (unsigned int)mpos);
        int aidx = f / NC;
        int cc = f - aidx * NC;
        int pp = aidx / NA;
        int a = aidx - pp * NA;
        int hh = pp / W;
        int ww = pp - hh * W;

        int ri = a / 3, si = a % 3;
        double ratio = (ri == 0) ? 0.5 : ((ri == 1) ? 1.0 : 2.0);
        double scale = (si == 0) ? 4.0 : ((si == 1) ? 8.0 : 16.0);
        double basew = (double)stride;
        double ctr = (basew - 1.0) * 0.5;
        double wsd = rint(sqrt(basew * basew / ratio));
        double hsd = rint(wsd * ratio);
        double ax1 = ctr - 0.5 * (wsd - 1.0), ay1 = ctr - 0.5 * (hsd - 1.0);
        double ax2 = ctr + 0.5 * (wsd - 1.0), ay2 = ctr + 0.5 * (hsd - 1.0);
        double aw = ax2 - ax1 + 1.0, ah = ay2 - ay1 + 1.0;
        double cxd = ax1 + 0.5 * (aw - 1.0), cyd = ay1 + 0.5 * (ah - 1.0);
        double swd = aw * scale, shd = ah * scale;
        float bx1 = (float)(cxd - 0.5 * (swd - 1.0));
        float by1 = (float)(cyd - 0.5 * (shd - 1.0));
        float bx2 = (float)(cxd + 0.5 * (swd - 1.0));
        float by2 = (float)(cyd + 0.5 * (shd - 1.0));
        float shx = (float)(ww * stride), shy = (float)(hh * stride);
        float Ax1 = shx + bx1, Ay1 = shy + by1, Ax2 = shx + bx2, Ay2 = shy + by2;

        size_t lbase = ((size_t)b * (NA * 4) + (size_t)a * 4) * (size_t)HW + (size_t)pp;
        float dx = loc[lbase];
        float dy = loc[lbase + HW];
        float dw = loc[lbase + 2 * (size_t)HW];
        float dh = loc[lbase + 3 * (size_t)HW];

        float ws = Ax2 - Ax1 + 1.0f, hs = Ay2 - Ay1 + 1.0f;
        float cx = Ax1 + 0.5f * (ws - 1.0f), cy = Ay1 + 0.5f * (hs - 1.0f);
        dw = fminf(fmaxf(dw, -LOG_MAX_F), LOG_MAX_F);
        dh = fminf(fmaxf(dh, -LOG_MAX_F), LOG_MAX_F);
        float pcx = dx * ws + cx, pcy = dy * hs + cy;
        float pw = expf(dw) * ws, ph = expf(dh) * hs;
        float x1 = pcx - 0.5f * (pw - 1.0f);
        float y1 = pcy - 0.5f * (ph - 1.0f);
        float x2 = pcx + 0.5f * (pw - 1.0f);
        float y2 = pcy + 0.5f * (ph - 1.0f);
        x1 = fminf(fmaxf(x1, 0.0f), imw - 1.0f);
        y1 = fminf(fmaxf(y1, 0.0f), imh - 1.0f);
        x2 = fminf(fmaxf(x2, 0.0f), imw - 1.0f);
        y2 = fminf(fmaxf(y2, 0.0f), imh - 1.0f);

        row[0] = x1; row[1] = y1; row[2] = x2; row[3] = y2;
        row[4] = score;
        row[5] = (float)(cc + 1);
    }

    // ---- last block per image: 3-way merge of sorted level lists ----
    __syncthreads();
    __shared__ int s_lastm;
    if (tid == 0) {
        __threadfence();
        unsigned int o = atomicAdd(&g_mdone[b], 1u);
        s_lastm = (o == 2u);
    }
    __syncthreads();
    if (!s_lastm) return;
    __threadfence();

    u64* A = sk;  // reuse smem (3000 u64 = 24KB)
    for (int i = tid; i < 3000; i += nt) A[i] = g_skey[b][i];
    __syncthreads();
    for (int i = tid; i < 3000; i += nt) {
        u64 k = A[i];
        int l = i / 1000;
        int r = i - l * 1000;
        int rank = r;
#pragma unroll
        for (int o = 0; o < 3; o++) {
            if (o == l) continue;
            const u64* arr = &A[o * 1000];
            int lo = 0, hi = 1000;
            while (lo < hi) {
                int mid = (lo + hi) >> 1;
                if (arr[mid] > k) lo = mid + 1; else hi = mid;
            }
            rank += lo;
        }
        g_spos[b][rank] = i;
        const float* rw = g_rois[b][i];
        float off = rw[5] * IMG_OFF;
        float a1 = rw[0] + off, b1 = rw[1] + off;
        float a2 = rw[2] + off, b2 = rw[3] + off;
        g_sx1[b][rank] = a1; g_sy1[b][rank] = b1;
        g_sx2[b][rank] = a2; g_sy2[b][rank] = b2;
        g_sar[b][rank] = (a2 - a1 + 1.0f) * (b2 - b1 + 1.0f);
    }
}

// ---------------- kernel 3: suppression bitmask + last-block greedy reduce ----------------
__global__ void __launch_bounds__(64) mask_reduce_kernel(float* __restrict__ out) {
    int b = blockIdx.y;
    int t = blockIdx.x;
    int ri = 0;
    while (t >= NCH - ri) { t -= NCH - ri; ri++; }
    int ci = ri + t;

    __shared__ float sx1[64], sy1[64], sx2[64], sy2[64], sar[64];
    int col0 = ci * 64;
    int c = col0 + threadIdx.x;
    if (c < 3000) {
        sx1[threadIdx.x] = g_sx1[b][c];
        sy1[threadIdx.x] = g_sy1[b][c];
        sx2[threadIdx.x] = g_sx2[b][c];
        sy2[threadIdx.x] = g_sy2[b][c];
        sar[threadIdx.x] = g_sar[b][c];
    }
    __syncthreads();

    int row = ri * 64 + threadIdx.x;
    if (row < 3000) {
        float X1 = g_sx1[b][row], Y1 = g_sy1[b][row];
        float X2 = g_sx2[b][row], Y2 = g_sy2[b][row];
        float AR = g_sar[b][row];
        u64 bits = 0ull;
        int jmax = min(64, 3000 - col0);
#pragma unroll 4
        for (int j = 0; j < jmax; j++) {
            int cidx = col0 + j;
            if (cidx <= row) continue;
            float ltx = fmaxf(X1, sx1[j]);
            float lty = fmaxf(Y1, sy1[j]);
            float rbx = fminf(X2, sx2[j]);
            float rby = fminf(Y2, sy2[j]);
            float w = fmaxf((rbx - ltx) + 1.0f, 0.0f);
            float h = fmaxf((rby - lty) + 1.0f, 0.0f);
            float inter = w * h;
            float iou = inter / ((AR + sar[j]) - inter);
            if (iou > 0.5f) bits |= (1ull << j);
        }
        g_mask[b][row * NCH + ci] = bits;
    }

    // ---- last block for image b performs the single-warp greedy reduce ----
    __syncthreads();
    __shared__ int s_last;
    if (threadIdx.x == 0) {
        __threadfence();
        unsigned int o = atomicAdd(&g_kdone[b], 1u);
        s_last = (o == (unsigned int)(NTILE - 1));
    }
    __syncthreads();
    if (!s_last) return;

    __shared__ int kept[TOPN];
    __shared__ int s_k;
    if (threadIdx.x < 32) {
        __threadfence();
        int lane = threadIdx.x;
        u64 r0 = 0ull, r1 = 0ull;
        int k = 0;
        const u64* mb = g_mask[b];
        int lane2 = lane + 32;
        bool has2 = lane2 < NCH;

        u64 cur0[8], cur1[8], nxt0[8], nxt1[8];
#pragma unroll
        for (int d = 0; d < 8; d++) {
            cur0[d] = mb[(size_t)d * NCH + lane];
            cur1[d] = has2 ? mb[(size_t)d * NCH + lane2] : 0ull;
        }
        for (int base = 0; base < 3000 && k < TOPN; base += 8) {
            int nb = base + 8;
#pragma unroll
            for (int d = 0; d < 8; d++) {
                int rr = nb + d;
                bool okr = rr < 3000;
                nxt0[d] = okr ? mb[(size_t)rr * NCH + lane] : 0ull;
                nxt1[d] = (okr && has2) ? mb[(size_t)rr * NCH + lane2] : 0ull;
            }
#pragma unroll
            for (int d = 0; d < 8; d++) {
                int i = base + d;
                int w = i >> 6;
                u64 tmp = (w < 32) ? r0 : r1;
                int owner = (w < 32) ? w : (w - 32);
                u64 val = __shfl_sync(0xFFFFFFFFu, tmp, owner);
                if (!((val >> (i & 63)) & 1ull)) {
                    if (lane == 0) kept[k] = i;
                    k++;
                    if (k == TOPN) break;
                    if (lane >= w) r0 |= cur0[d];
                    if (has2 && lane2 >= w) r1 |= cur1[d];
                }
            }
#pragma unroll
            for (int d = 0; d < 8; d++) { cur0[d] = nxt0[d]; cur1[d] = nxt1[d]; }
        }
        __syncwarp();
        if (lane == 0) s_k = k;
        __syncwarp();
        k = s_k;

        for (int r = lane; r < TOPN; r += 32) {
            float* o = out + ((size_t)b * TOPN + r) * 7;
            if (r < k) {
                int pos = g_spos[b][kept[r]];
                const float* rw = g_rois[b][pos];
                o[0] = (float)b;
                o[1] = rw[0]; o[2] = rw[1]; o[3] = rw[2]; o[4] = rw[3];
                o[5] = rw[4]; o[6] = rw[5];
            } else {
                for (int q = 0; q < 7; q++) o[q] = 0.0f;
            }
        }

        // re-zero this image's counters for the next graph replay
        if (lane == 0) {
            g_kdone[b] = 0;
            g_mdone[b] = 0;
#pragma unroll
            for (int l = 0; l < 3; l++) {
                g_cnt[b * 3 + l] = 0;
                g_done[b * 3 + l] = 0;
            }
        }
    }
}

// ---------------- host launcher ----------------
extern "C" void kernel_launch(void* const* d_in, const int* in_sizes, int n_in,
                              void* d_out, int out_size) {
    (void)in_sizes; (void)n_in; (void)out_size;
    const float4* cls0 = (const float4*)d_in[0];
    const float*  loc0 = (const float*)d_in[1];
    const float4* cls1 = (const float4*)d_in[2];
    const float*  loc1 = (const float*)d_in[3];
    const float4* cls2 = (const float4*)d_in[4];
    const float*  loc2 = (const float*)d_in[5];
    const float*  info = (const float*)d_in[6];
    float* out = (float*)d_out;

    cudaFuncSetAttribute(topk_decode_kernel,
                         cudaFuncAttributeMaxDynamicSharedMemorySize, 65536);

    passA_kernel<<<1536, 256>>>(cls0, cls1, cls2);
    topk_decode_kernel<<<12, 1024, 65536>>>(cls0, cls1, cls2, loc0, loc1, loc2, info);
    mask_reduce_kernel<<<dim3(NTILE, NB), 64>>>(out);
}